// round 10
// baseline (speedup 1.0000x reference)
#include <cuda_runtime.h>
#include <math.h>

// Ewald real-space sum, B=4 equal contiguous batches, n=8192, nq=8.
// Lower-triangle 128x128 tiles (off-diag doubled), j-range split in 4.
// Kernel function f(s) = erf(sqrt(s/2))/sqrt(s) evaluated via a 1024-entry
// piecewise-linear LUT indexed by the float bits of s (32 segments/octave,
// s in [2^-20, 4096)). Zero MUFU in the hot loop, 16 fma-elements per pair.

#define NQ      8
#define TS      128          // i-rows per block (= threads)
#define JSPLIT  4
#define JH      (TS/JSPLIT)  // 32 j per block
#define NBATCH  4

#define PAIR_SCALE 7.1661475615124055f   // NORM/(4*pi)
#define SELF_SCALE 5.7174058735714600f   // NORM/(2*pi)^1.5

// A&S 7.1.26 for the (accurate, off-hot-path) table build
#define AS_A1  0.254829592f
#define AS_A2 -0.284496736f
#define AS_A3  1.421413741f
#define AS_A4 -1.453152027f
#define AS_A5  1.061405429f
#define AS_P2  0.23164189f      // p / sqrt(2)
#define NEXP  -0.7213475204f    // -0.5 * log2(e)

#define LUT_N    1024
#define LUT_BIAS 3424           // (127-20)<<5 : s = 2^-20 -> idx 0

__device__ __forceinline__ float fast_ex2(float x) {
    float y; asm("ex2.approx.f32 %0, %1;" : "=f"(y) : "f"(x)); return y;
}

// g(s) = erf(sqrt(s/2)) / sqrt(s), accurate eval for table boundaries
__device__ __forceinline__ float g_of_s(float s) {
    const float d  = sqrtf(s);
    const float tt = 1.0f / fmaf(AS_P2, d, 1.0f);
    float poly = fmaf(AS_A5, tt, AS_A4);
    poly = fmaf(poly, tt, AS_A3);
    poly = fmaf(poly, tt, AS_A2);
    poly = fmaf(poly, tt, AS_A1);
    poly = poly * tt;
    const float erfv = fmaf(-poly, fast_ex2(s * NEXP), 1.0f);
    return erfv / d;
}

struct SmemT {
    float2 lut[LUT_N];          // (slope, intercept) per 1/32-octave of s
    float4 shq0[JH];
    float4 shq1[JH];
    float4 shr[JH];
    float  wsum[TS / 32];
};

template<bool DIAG>
__device__ __forceinline__ void mainloop(
    const SmemT& sm,
    const float4& qi0, const float4& qi1,
    float rix, float riy, float riz,
    float& acc0, float& acc1)
{
#pragma unroll 8
    for (int jj = 0; jj < JH; ++jj) {
        const float4 qj0 = sm.shq0[jj];
        const float4 qj1 = sm.shq1[jj];
        const float4 rj  = sm.shr[jj];

        float qq = qi0.x * qj0.x;
        qq = fmaf(qi0.y, qj0.y, qq);
        qq = fmaf(qi0.z, qj0.z, qq);
        qq = fmaf(qi0.w, qj0.w, qq);
        qq = fmaf(qi1.x, qj1.x, qq);
        qq = fmaf(qi1.y, qj1.y, qq);
        qq = fmaf(qi1.z, qj1.z, qq);
        qq = fmaf(qi1.w, qj1.w, qq);

        const float dx = rix - rj.x;
        const float dy = riy - rj.y;
        const float dz = riz - rj.z;
        float s = dx * dx;
        s = fmaf(dy, dy, s);
        s = fmaf(dz, dz, s);

        // log-scale LUT index from float bits: 32 segments per octave.
        // s < 4096 always (30A box), so no upper clamp needed.
        int idx = (int)(__float_as_uint(s) >> 18) - LUT_BIAS;
        idx = max(idx, 0);
        const float2 c = sm.lut[idx];
        float f = fmaf(c.x, s, c.y);           // erf(sqrt(s/2))/sqrt(s)

        if (DIAG) f = (s > 0.0f) ? f : 0.0f;   // diag s is exactly 0

        if (jj & 1) acc1 = fmaf(qq, f, acc1);
        else        acc0 = fmaf(qq, f, acc0);
    }
}

__global__ __launch_bounds__(TS)
void ewald_kernel(const float* __restrict__ q,
                  const float* __restrict__ r,
                  float* __restrict__ out,
                  int nb)
{
    __shared__ SmemT sm;

    const int t = threadIdx.x;

    // linear block index -> lower-triangle tile (bx, by), by <= bx
    const int k = blockIdx.x;
    int bx = (int)((__fsqrt_rn(8.0f * (float)k + 1.0f) - 1.0f) * 0.5f);
    while ((bx + 1) * (bx + 2) / 2 <= k) ++bx;
    while (bx * (bx + 1) / 2 > k)       --bx;
    const int by = k - bx * (bx + 1) / 2;

    const int ys = blockIdx.y;
    const int b  = blockIdx.z;
    const int i  = b * nb + bx * TS + t;
    const int j0 = b * nb + by * TS + ys * JH;

    // ---- build LUT: segment kk covers s in [s0, s1), linear fit ----
    for (int kk = t; kk < LUT_N; kk += TS) {
        const float s0 = __uint_as_float((unsigned)(kk + LUT_BIAS)     << 18);
        const float s1 = __uint_as_float((unsigned)(kk + 1 + LUT_BIAS) << 18);
        const float g0 = g_of_s(s0);
        const float g1 = g_of_s(s1);
        const float slope = (g1 - g0) / (s1 - s0);
        sm.lut[kk] = make_float2(slope, fmaf(-slope, s0, g0));
    }

    // ---- stage j tile ----
    if (t < JH) {
        const int j = j0 + t;
        sm.shq0[t] = *reinterpret_cast<const float4*>(q + (size_t)j * NQ);
        sm.shq1[t] = *reinterpret_cast<const float4*>(q + (size_t)j * NQ + 4);
        sm.shr[t]  = make_float4(r[(size_t)j * 3 + 0],
                                 r[(size_t)j * 3 + 1],
                                 r[(size_t)j * 3 + 2], 0.0f);
    }

    // ---- per-thread i data ----
    const float4 qi0 = *reinterpret_cast<const float4*>(q + (size_t)i * NQ);
    const float4 qi1 = *reinterpret_cast<const float4*>(q + (size_t)i * NQ + 4);
    const float rix = r[(size_t)i * 3 + 0];
    const float riy = r[(size_t)i * 3 + 1];
    const float riz = r[(size_t)i * 3 + 2];

    __syncthreads();

    float acc0 = 0.0f, acc1 = 0.0f;
    const bool diag = (bx == by);
    if (diag) mainloop<true >(sm, qi0, qi1, rix, riy, riz, acc0, acc1);
    else      mainloop<false>(sm, qi0, qi1, rix, riy, riz, acc0, acc1);

    float contrib = (acc0 + acc1) * (diag ? PAIR_SCALE : 2.0f * PAIR_SCALE);

    // self-interaction: exactly once per i-row
    if (by == 0 && ys == 0) {
        float qsq = qi0.x * qi0.x;
        qsq = fmaf(qi0.y, qi0.y, qsq);
        qsq = fmaf(qi0.z, qi0.z, qsq);
        qsq = fmaf(qi0.w, qi0.w, qsq);
        qsq = fmaf(qi1.x, qi1.x, qsq);
        qsq = fmaf(qi1.y, qi1.y, qsq);
        qsq = fmaf(qi1.z, qi1.z, qsq);
        qsq = fmaf(qi1.w, qi1.w, qsq);
        contrib = fmaf(qsq, SELF_SCALE, contrib);
    }

    // block reduction -> one atomic
#pragma unroll
    for (int o = 16; o > 0; o >>= 1)
        contrib += __shfl_xor_sync(0xFFFFFFFFu, contrib, o);
    if ((t & 31) == 0) sm.wsum[t >> 5] = contrib;
    __syncthreads();
    if (t == 0) {
        float ssum = sm.wsum[0];
#pragma unroll
        for (int w = 1; w < TS / 32; ++w) ssum += sm.wsum[w];
        atomicAdd(&out[b], ssum);
    }
}

extern "C" void kernel_launch(void* const* d_in, const int* in_sizes, int n_in,
                              void* d_out, int out_size)
{
    const float* q = (const float*)d_in[0];
    const float* r = (const float*)d_in[1];

    const int n      = in_sizes[1] / 3;             // 8192
    const int nb     = n / NBATCH;                  // 2048
    const int ntiles = nb / TS;                     // 16
    const int ntri   = ntiles * (ntiles + 1) / 2;   // 136

    float* out = (float*)d_out;
    cudaMemsetAsync(out, 0, NBATCH * sizeof(float));

    dim3 grid(ntri, JSPLIT, NBATCH);                // (136, 4, 4) = 2176 blocks
    ewald_kernel<<<grid, TS>>>(q, r, out, nb);
}

// round 11
// speedup vs baseline: 1.2966x; 1.2966x over previous
#include <cuda_runtime.h>
#include <math.h>

// Ewald real-space sum, B=4 equal contiguous batches, n=8192, nq=8.
// Lower-triangle 256x256 tiles (off-diag doubled), j-range split in 8.
// Each thread handles TWO i-rows (t, t+128): two independent dependency
// chains per thread to hide the erf-chain latency. Branchless A&S erf.
// Single-kernel graph: accumulate in __device__ globals, last block writes
// d_out and resets state (replay-safe), no memset node.

#define NQ      8
#define TSI     256          // i-rows per tile
#define THREADS 128          // threads per block (2 i-rows each)
#define JSPLIT  8
#define JH      (TSI/JSPLIT) // 32 j per block
#define NBATCH  4
#define NTILES  8            // 2048/256
#define NTRI    36           // 8*9/2
#define NBLOCKS (NTRI*JSPLIT*NBATCH)   // 1152

#define PAIR_SCALE 7.1661475615124055f   // NORM/(4*pi)
#define SELF_SCALE 5.7174058735714600f   // NORM/(2*pi)^1.5

// A&S 7.1.26 (abs err 1.5e-7)
#define AS_A1  0.254829592f
#define AS_A2 -0.284496736f
#define AS_A3  1.421413741f
#define AS_A4 -1.453152027f
#define AS_A5  1.061405429f
#define AS_P2  0.23164189f      // p / sqrt(2)
#define NEXP  -0.7213475204f    // -0.5 * log2(e)

__device__ float    g_acc[NBATCH];   // zero-initialized at module load
__device__ unsigned g_cnt;           // zero-initialized

__device__ __forceinline__ float fast_rsq(float x) {
    float y; asm("rsqrt.approx.f32 %0, %1;" : "=f"(y) : "f"(x)); return y;
}
__device__ __forceinline__ float fast_rcp(float x) {
    float y; asm("rcp.approx.f32 %0, %1;" : "=f"(y) : "f"(x)); return y;
}
__device__ __forceinline__ float fast_ex2(float x) {
    float y; asm("ex2.approx.f32 %0, %1;" : "=f"(y) : "f"(x)); return y;
}

// f(s) = erf(sqrt(s/2))/sqrt(s); diag guard applied by caller
__device__ __forceinline__ float pair_f(float s) {
    const float rsq = fast_rsq(s);
    const float d   = s * rsq;
    const float u   = fmaf(AS_P2, d, 1.0f);
    const float tt  = fast_rcp(u);
    float poly = fmaf(AS_A5, tt, AS_A4);
    poly = fmaf(poly, tt, AS_A3);
    poly = fmaf(poly, tt, AS_A2);
    poly = fmaf(poly, tt, AS_A1);
    poly = poly * tt;
    const float e    = fast_ex2(s * NEXP);
    const float erfv = fmaf(-poly, e, 1.0f);
    return erfv * rsq;
}

struct SmemT {
    float4 shq0[JH];
    float4 shq1[JH];
    float4 shr[JH];
    float  wsum[THREADS / 32];
};

template<bool DIAG>
__device__ __forceinline__ void mainloop(
    const SmemT& sm,
    const float4& p0, const float4& p1,     // q of i-row A
    const float4& q0, const float4& q1,     // q of i-row B
    float ax, float ay, float az,
    float bxx, float byy, float bzz,
    float& accA, float& accB)
{
#pragma unroll 4
    for (int jj = 0; jj < JH; ++jj) {
        const float4 qj0 = sm.shq0[jj];
        const float4 qj1 = sm.shq1[jj];
        const float4 rj  = sm.shr[jj];

        // two independent charge dot-products
        float qqA = p0.x * qj0.x;
        float qqB = q0.x * qj0.x;
        qqA = fmaf(p0.y, qj0.y, qqA);  qqB = fmaf(q0.y, qj0.y, qqB);
        qqA = fmaf(p0.z, qj0.z, qqA);  qqB = fmaf(q0.z, qj0.z, qqB);
        qqA = fmaf(p0.w, qj0.w, qqA);  qqB = fmaf(q0.w, qj0.w, qqB);
        qqA = fmaf(p1.x, qj1.x, qqA);  qqB = fmaf(q1.x, qj1.x, qqB);
        qqA = fmaf(p1.y, qj1.y, qqA);  qqB = fmaf(q1.y, qj1.y, qqB);
        qqA = fmaf(p1.z, qj1.z, qqA);  qqB = fmaf(q1.z, qj1.z, qqB);
        qqA = fmaf(p1.w, qj1.w, qqA);  qqB = fmaf(q1.w, qj1.w, qqB);

        // two independent distances
        const float dxA = ax - rj.x,  dxB = bxx - rj.x;
        const float dyA = ay - rj.y,  dyB = byy - rj.y;
        const float dzA = az - rj.z,  dzB = bzz - rj.z;
        float sA = dxA * dxA;         float sB = dxB * dxB;
        sA = fmaf(dyA, dyA, sA);      sB = fmaf(dyB, dyB, sB);
        sA = fmaf(dzA, dzA, sA);      sB = fmaf(dzB, dzB, sB);

        float fA = pair_f(sA);
        float fB = pair_f(sB);
        if (DIAG) {
            fA = (sA > 0.0f) ? fA : 0.0f;   // diag s is exactly 0 at i==j
            fB = (sB > 0.0f) ? fB : 0.0f;
        }
        accA = fmaf(qqA, fA, accA);
        accB = fmaf(qqB, fB, accB);
    }
}

__device__ __forceinline__ float qsq8(const float4& a, const float4& b) {
    float s = a.x * a.x;
    s = fmaf(a.y, a.y, s);  s = fmaf(a.z, a.z, s);  s = fmaf(a.w, a.w, s);
    s = fmaf(b.x, b.x, s);  s = fmaf(b.y, b.y, s);
    s = fmaf(b.z, b.z, s);  s = fmaf(b.w, b.w, s);
    return s;
}

__global__ __launch_bounds__(THREADS, 8)
void ewald_kernel(const float* __restrict__ q,
                  const float* __restrict__ r,
                  float* __restrict__ out,
                  int nb)
{
    __shared__ SmemT sm;

    const int t = threadIdx.x;

    // linear block index -> lower-triangle tile (bx, by), by <= bx
    const int k = blockIdx.x;
    int bx = (int)((__fsqrt_rn(8.0f * (float)k + 1.0f) - 1.0f) * 0.5f);
    while ((bx + 1) * (bx + 2) / 2 <= k) ++bx;
    while (bx * (bx + 1) / 2 > k)       --bx;
    const int by = k - bx * (bx + 1) / 2;

    const int ys = blockIdx.y;
    const int b  = blockIdx.z;
    const int iA = b * nb + bx * TSI + t;            // first i-row
    const int iB = iA + THREADS;                     // second i-row
    const int j0 = b * nb + by * TSI + ys * JH;

    // stage j tile (first JH threads)
    if (t < JH) {
        const int j = j0 + t;
        sm.shq0[t] = *reinterpret_cast<const float4*>(q + (size_t)j * NQ);
        sm.shq1[t] = *reinterpret_cast<const float4*>(q + (size_t)j * NQ + 4);
        sm.shr[t]  = make_float4(r[(size_t)j * 3 + 0],
                                 r[(size_t)j * 3 + 1],
                                 r[(size_t)j * 3 + 2], 0.0f);
    }

    // per-thread i data (two rows)
    const float4 p0 = *reinterpret_cast<const float4*>(q + (size_t)iA * NQ);
    const float4 p1 = *reinterpret_cast<const float4*>(q + (size_t)iA * NQ + 4);
    const float4 q0 = *reinterpret_cast<const float4*>(q + (size_t)iB * NQ);
    const float4 q1 = *reinterpret_cast<const float4*>(q + (size_t)iB * NQ + 4);
    const float ax  = r[(size_t)iA * 3 + 0];
    const float ay  = r[(size_t)iA * 3 + 1];
    const float az  = r[(size_t)iA * 3 + 2];
    const float bxx = r[(size_t)iB * 3 + 0];
    const float byy = r[(size_t)iB * 3 + 1];
    const float bzz = r[(size_t)iB * 3 + 2];

    __syncthreads();

    float accA = 0.0f, accB = 0.0f;
    const bool diag = (bx == by);
    if (diag) mainloop<true >(sm, p0, p1, q0, q1, ax, ay, az, bxx, byy, bzz, accA, accB);
    else      mainloop<false>(sm, p0, p1, q0, q1, ax, ay, az, bxx, byy, bzz, accA, accB);

    float contrib = (accA + accB) * (diag ? PAIR_SCALE : 2.0f * PAIR_SCALE);

    // self-interaction: exactly once per i-row
    if (by == 0 && ys == 0)
        contrib = fmaf(qsq8(p0, p1) + qsq8(q0, q1), SELF_SCALE, contrib);

    // block reduction
#pragma unroll
    for (int o = 16; o > 0; o >>= 1)
        contrib += __shfl_xor_sync(0xFFFFFFFFu, contrib, o);
    if ((t & 31) == 0) sm.wsum[t >> 5] = contrib;
    __syncthreads();

    if (t == 0) {
        float ssum = sm.wsum[0];
#pragma unroll
        for (int w = 1; w < THREADS / 32; ++w) ssum += sm.wsum[w];
        atomicAdd(&g_acc[b], ssum);
        __threadfence();
        const unsigned ticket = atomicAdd(&g_cnt, 1u);
        if (ticket == NBLOCKS - 1) {
            // last block: publish results and reset state for graph replay
#pragma unroll
            for (int bb = 0; bb < NBATCH; ++bb) {
                out[bb] = g_acc[bb];
                g_acc[bb] = 0.0f;
            }
            g_cnt = 0u;
            __threadfence();
        }
    }
}

extern "C" void kernel_launch(void* const* d_in, const int* in_sizes, int n_in,
                              void* d_out, int out_size)
{
    const float* q = (const float*)d_in[0];
    const float* r = (const float*)d_in[1];

    const int n  = in_sizes[1] / 3;      // 8192
    const int nb = n / NBATCH;           // 2048

    dim3 grid(NTRI, JSPLIT, NBATCH);     // (36, 8, 4) = 1152 blocks
    ewald_kernel<<<grid, THREADS>>>(q, r, (float*)d_out, nb);
}

// round 13
// speedup vs baseline: 1.3870x; 1.0698x over previous
#include <cuda_runtime.h>
#include <math.h>

// Ewald real-space sum, B=4 equal contiguous batches, n=8192, nq=8.
// Lower-triangle 256x256 tiles (off-diag doubled), j-range split in 8,
// 2 i-rows per thread (ILP). Key trick: erf(d/sqrt2)==1 to 3e-5 for d>3,
// and only ~0.4% of pairs in a 30A box are closer -> f = rsqrt(s) on the
// fast path; a warp-uniform vote triggers the A&S correction block only
// when some lane has s < 9. Single-kernel graph via __device__ accumulators.

#define NQ      8
#define TSI     256          // i-rows per tile
#define THREADS 128          // threads per block (2 i-rows each)
#define JSPLIT  8
#define JH      (TSI/JSPLIT) // 32 j per block
#define NBATCH  4
#define NTRI    36           // 8*9/2 triangle tiles
#define NBLOCKS (NTRI*JSPLIT*NBATCH)   // 1152

#define PAIR_SCALE 7.1661475615124055f   // NORM/(4*pi)
#define SELF_SCALE 5.7174058735714600f   // NORM/(2*pi)^1.5

// A&S 7.1.25 (3-term, abs err 2.5e-5) -- only used for the ~0.4% close pairs
#define AS3_A1  0.3480242f
#define AS3_A2 -0.0958798f
#define AS3_A3  0.7478556f
#define AS3_P2  0.3326862f      // p / sqrt(2), p = 0.47047
#define NEXP   -0.7213475204f   // -0.5 * log2(e)
#define S_CUT   9.0f            // d < 3 -> run correction

__device__ float    g_acc[NBATCH];   // zero-initialized at module load
__device__ unsigned g_cnt;

__device__ __forceinline__ float fast_rsq(float x) {
    float y; asm("rsqrt.approx.f32 %0, %1;" : "=f"(y) : "f"(x)); return y;
}
__device__ __forceinline__ float fast_rcp(float x) {
    float y; asm("rcp.approx.f32 %0, %1;" : "=f"(y) : "f"(x)); return y;
}
__device__ __forceinline__ float fast_ex2(float x) {
    float y; asm("ex2.approx.f32 %0, %1;" : "=f"(y) : "f"(x)); return y;
}

// corrected f for s < S_CUT; keeps the fast value otherwise
__device__ __forceinline__ float erf_corr(float s, float rsq, float ffast) {
    const float d  = s * rsq;
    const float tt = fast_rcp(fmaf(AS3_P2, d, 1.0f));
    float poly = fmaf(AS3_A3, tt, AS3_A2);
    poly = fmaf(poly, tt, AS3_A1);
    poly = poly * tt;
    const float erfv = fmaf(-poly, fast_ex2(s * NEXP), 1.0f);
    const float fc   = erfv * rsq;
    return (s < S_CUT) ? fc : ffast;
}

struct SmemT {
    float4 shq0[JH];
    float4 shq1[JH];
    float4 shr[JH];
    float  wsum[THREADS / 32];
};

template<bool DIAG>
__device__ __forceinline__ void mainloop(
    const SmemT& sm,
    const float4& p0, const float4& p1,
    const float4& q0, const float4& q1,
    float ax, float ay, float az,
    float bxx, float byy, float bzz,
    float& accA, float& accB)
{
#pragma unroll 4
    for (int jj = 0; jj < JH; ++jj) {
        const float4 qj0 = sm.shq0[jj];
        const float4 qj1 = sm.shq1[jj];
        const float4 rj  = sm.shr[jj];

        float qqA = p0.x * qj0.x;
        float qqB = q0.x * qj0.x;
        qqA = fmaf(p0.y, qj0.y, qqA);  qqB = fmaf(q0.y, qj0.y, qqB);
        qqA = fmaf(p0.z, qj0.z, qqA);  qqB = fmaf(q0.z, qj0.z, qqB);
        qqA = fmaf(p0.w, qj0.w, qqA);  qqB = fmaf(q0.w, qj0.w, qqB);
        qqA = fmaf(p1.x, qj1.x, qqA);  qqB = fmaf(q1.x, qj1.x, qqB);
        qqA = fmaf(p1.y, qj1.y, qqA);  qqB = fmaf(q1.y, qj1.y, qqB);
        qqA = fmaf(p1.z, qj1.z, qqA);  qqB = fmaf(q1.z, qj1.z, qqB);
        qqA = fmaf(p1.w, qj1.w, qqA);  qqB = fmaf(q1.w, qj1.w, qqB);

        const float dxA = ax - rj.x,  dxB = bxx - rj.x;
        const float dyA = ay - rj.y,  dyB = byy - rj.y;
        const float dzA = az - rj.z,  dzB = bzz - rj.z;
        float sA = dxA * dxA;         float sB = dxB * dxB;
        sA = fmaf(dyA, dyA, sA);      sB = fmaf(dyB, dyB, sB);
        sA = fmaf(dzA, dzA, sA);      sB = fmaf(dzB, dzB, sB);

        const float rsqA = fast_rsq(sA);
        const float rsqB = fast_rsq(sB);
        float fA = rsqA;              // erf==1 for d>3 (to 3e-5)
        float fB = rsqB;

        // warp-uniform rare path: some lane closer than 3 Angstrom
        if (__any_sync(0xFFFFFFFFu, fminf(sA, sB) < S_CUT)) {
            fA = erf_corr(sA, rsqA, fA);
            fB = erf_corr(sB, rsqB, fB);
            if (DIAG) {               // diag s is exactly 0 -> term is 0
                fA = (sA > 0.0f) ? fA : 0.0f;
                fB = (sB > 0.0f) ? fB : 0.0f;
            }
        }

        accA = fmaf(qqA, fA, accA);
        accB = fmaf(qqB, fB, accB);
    }
}

__device__ __forceinline__ float qsq8(const float4& a, const float4& b) {
    float s = a.x * a.x;
    s = fmaf(a.y, a.y, s);  s = fmaf(a.z, a.z, s);  s = fmaf(a.w, a.w, s);
    s = fmaf(b.x, b.x, s);  s = fmaf(b.y, b.y, s);
    s = fmaf(b.z, b.z, s);  s = fmaf(b.w, b.w, s);
    return s;
}

__global__ __launch_bounds__(THREADS, 8)
void ewald_kernel(const float* __restrict__ q,
                  const float* __restrict__ r,
                  float* __restrict__ out,
                  int nb)
{
    __shared__ SmemT sm;

    const int t = threadIdx.x;

    const int k = blockIdx.x;
    int bx = (int)((__fsqrt_rn(8.0f * (float)k + 1.0f) - 1.0f) * 0.5f);
    while ((bx + 1) * (bx + 2) / 2 <= k) ++bx;
    while (bx * (bx + 1) / 2 > k)       --bx;
    const int by = k - bx * (bx + 1) / 2;

    const int ys = blockIdx.y;
    const int b  = blockIdx.z;
    const int iA = b * nb + bx * TSI + t;
    const int iB = iA + THREADS;
    const int j0 = b * nb + by * TSI + ys * JH;

    if (t < JH) {
        const int j = j0 + t;
        sm.shq0[t] = *reinterpret_cast<const float4*>(q + (size_t)j * NQ);
        sm.shq1[t] = *reinterpret_cast<const float4*>(q + (size_t)j * NQ + 4);
        sm.shr[t]  = make_float4(r[(size_t)j * 3 + 0],
                                 r[(size_t)j * 3 + 1],
                                 r[(size_t)j * 3 + 2], 0.0f);
    }

    const float4 p0 = *reinterpret_cast<const float4*>(q + (size_t)iA * NQ);
    const float4 p1 = *reinterpret_cast<const float4*>(q + (size_t)iA * NQ + 4);
    const float4 q0 = *reinterpret_cast<const float4*>(q + (size_t)iB * NQ);
    const float4 q1 = *reinterpret_cast<const float4*>(q + (size_t)iB * NQ + 4);
    const float ax  = r[(size_t)iA * 3 + 0];
    const float ay  = r[(size_t)iA * 3 + 1];
    const float az  = r[(size_t)iA * 3 + 2];
    const float bxx = r[(size_t)iB * 3 + 0];
    const float byy = r[(size_t)iB * 3 + 1];
    const float bzz = r[(size_t)iB * 3 + 2];

    __syncthreads();

    float accA = 0.0f, accB = 0.0f;
    const bool diag = (bx == by);
    if (diag) mainloop<true >(sm, p0, p1, q0, q1, ax, ay, az, bxx, byy, bzz, accA, accB);
    else      mainloop<false>(sm, p0, p1, q0, q1, ax, ay, az, bxx, byy, bzz, accA, accB);

    float contrib = (accA + accB) * (diag ? PAIR_SCALE : 2.0f * PAIR_SCALE);

    if (by == 0 && ys == 0)
        contrib = fmaf(qsq8(p0, p1) + qsq8(q0, q1), SELF_SCALE, contrib);

#pragma unroll
    for (int o = 16; o > 0; o >>= 1)
        contrib += __shfl_xor_sync(0xFFFFFFFFu, contrib, o);
    if ((t & 31) == 0) sm.wsum[t >> 5] = contrib;
    __syncthreads();

    if (t == 0) {
        float ssum = sm.wsum[0];
#pragma unroll
        for (int w = 1; w < THREADS / 32; ++w) ssum += sm.wsum[w];
        atomicAdd(&g_acc[b], ssum);
        __threadfence();
        const unsigned ticket = atomicAdd(&g_cnt, 1u);
        if (ticket == NBLOCKS - 1) {
            // last block: publish and reset for graph replay
#pragma unroll
            for (int bb = 0; bb < NBATCH; ++bb) {
                out[bb] = g_acc[bb];
                g_acc[bb] = 0.0f;
            }
            g_cnt = 0u;
            __threadfence();
        }
    }
}

extern "C" void kernel_launch(void* const* d_in, const int* in_sizes, int n_in,
                              void* d_out, int out_size)
{
    const float* q = (const float*)d_in[0];
    const float* r = (const float*)d_in[1];

    const int n  = in_sizes[1] / 3;      // 8192
    const int nb = n / NBATCH;           // 2048

    dim3 grid(NTRI, JSPLIT, NBATCH);     // (36, 8, 4) = 1152 blocks
    ewald_kernel<<<grid, THREADS>>>(q, r, (float*)d_out, nb);
}